// round 8
// baseline (speedup 1.0000x reference)
#include <cuda_runtime.h>
#include <cuda_bf16.h>
#include <math.h>
#include <stdint.h>

#define NB 2
#define NS 2048
#define ND 1024
#define NH 16
#define HDIM 64
#define MROWS (NB*NS)
#define RWORDS (ND/2)          // 512 u32 words per 1024-elem bf16 row

// ---- static scratch (no allocations allowed) ----
// input planes (rows = B*S, 512 words each)
__device__ uint32_t g_inqh[MROWS*RWORDS], g_inql[MROWS*RWORDS];
__device__ uint32_t g_inkh[MROWS*RWORDS], g_inkl[MROWS*RWORDS];
__device__ uint32_t g_invh[MROWS*RWORDS], g_invl[MROWS*RWORDS];
// weight planes (4 matrices x 1024 rows x 512 words)
__device__ uint32_t g_wh[4*ND*RWORDS], g_wl[4*ND*RWORDS];
// projected q/k/v planes, head layout [b*H+h][s][e]
__device__ uint32_t g_qh[NB*NH*NS*HDIM/2], g_ql[NB*NH*NS*HDIM/2];
__device__ uint32_t g_kh[NB*NH*NS*HDIM/2], g_kl[NB*NH*NS*HDIM/2];
__device__ uint32_t g_vh[NB*NH*NS*HDIM/2], g_vl[NB*NH*NS*HDIM/2];
// attention output planes [b][s][h*64+e]
__device__ uint32_t g_ch[MROWS*RWORDS], g_cl[MROWS*RWORDS];

#define QSCALE 0.18033688011f      // 0.125 * log2(e)

#define MMA16816(c, a, b) \
  asm volatile("mma.sync.aligned.m16n8k16.row.col.f32.bf16.bf16.f32 " \
    "{%0,%1,%2,%3}, {%4,%5,%6,%7}, {%8,%9}, {%0,%1,%2,%3};" \
    : "+f"((c)[0]), "+f"((c)[1]), "+f"((c)[2]), "+f"((c)[3]) \
    : "r"((a)[0]), "r"((a)[1]), "r"((a)[2]), "r"((a)[3]), \
      "r"((b)[0]), "r"((b)[1]))

__device__ __forceinline__ void cvt_pair(float x, float y, uint32_t& hi, uint32_t& lo) {
    __nv_bfloat162 h = __floats2bfloat162_rn(x, y);
    float hx = __bfloat162float(__low2bfloat16(h));
    float hy = __bfloat162float(__high2bfloat16(h));
    __nv_bfloat162 l = __floats2bfloat162_rn(x - hx, y - hy);
    hi = *reinterpret_cast<uint32_t*>(&h);
    lo = *reinterpret_cast<uint32_t*>(&l);
}
__device__ __forceinline__ float ex2f(float x) {
    float y; asm("ex2.approx.ftz.f32 %0, %1;" : "=f"(y) : "f"(x)); return y;
}
__device__ __forceinline__ uint32_t smem_u32(const void* p) {
    uint32_t a;
    asm("{ .reg .u64 t; cvta.to.shared.u64 t, %1; cvt.u32.u64 %0, t; }" : "=r"(a) : "l"(p));
    return a;
}
__device__ __forceinline__ void ldsm_x4(uint32_t& r0, uint32_t& r1, uint32_t& r2, uint32_t& r3,
                                        uint32_t a) {
    asm volatile("ldmatrix.sync.aligned.m8n8.x4.shared.b16 {%0,%1,%2,%3}, [%4];"
                 : "=r"(r0), "=r"(r1), "=r"(r2), "=r"(r3) : "r"(a));
}
__device__ __forceinline__ void ldsm_x4_t(uint32_t& r0, uint32_t& r1, uint32_t& r2, uint32_t& r3,
                                          uint32_t a) {
    asm volatile("ldmatrix.sync.aligned.m8n8.x4.trans.shared.b16 {%0,%1,%2,%3}, [%4];"
                 : "=r"(r0), "=r"(r1), "=r"(r2), "=r"(r3) : "r"(a));
}
__device__ __forceinline__ void cp16(uint32_t dst, const void* src) {
    asm volatile("cp.async.cg.shared.global [%0], [%1], 16;" :: "r"(dst), "l"(src) : "memory");
}
__device__ __forceinline__ void cp_commit() {
    asm volatile("cp.async.commit_group;" ::: "memory");
}
template<int N> __device__ __forceinline__ void cp_wait() {
    asm volatile("cp.async.wait_group %0;" :: "n"(N) : "memory");
}

// ---------------------------------------------------------------------------
// fp32 -> bf16 hi/lo plane converter (grid-stride free, exact sizes)
// ---------------------------------------------------------------------------
__global__ __launch_bounds__(256) void cvt_planes(
    const float* s0, uint32_t* h0, uint32_t* l0,
    const float* s1, uint32_t* h1, uint32_t* l1,
    const float* s2, uint32_t* h2, uint32_t* l2,
    const float* s3, uint32_t* h3, uint32_t* l3)
{
    const float* s; uint32_t *ph, *pl;
    switch (blockIdx.z) {
        case 0: s = s0; ph = h0; pl = l0; break;
        case 1: s = s1; ph = h1; pl = l1; break;
        case 2: s = s2; ph = h2; pl = l2; break;
        default: s = s3; ph = h3; pl = l3; break;
    }
    int i = blockIdx.x * 256 + threadIdx.x;   // one uint4 (8 floats) per thread
    float4 a = ((const float4*)s)[2 * i];
    float4 b = ((const float4*)s)[2 * i + 1];
    uint32_t h[4], l[4];
    cvt_pair(a.x, a.y, h[0], l[0]);
    cvt_pair(a.z, a.w, h[1], l[1]);
    cvt_pair(b.x, b.y, h[2], l[2]);
    cvt_pair(b.z, b.w, h[3], l[3]);
    ((uint4*)ph)[i] = make_uint4(h[0], h[1], h[2], h[3]);
    ((uint4*)pl)[i] = make_uint4(l[0], l[1], l[2], l[3]);
}

// ---------------------------------------------------------------------------
// Plane GEMM: C[m][n] = sum_k A[m,k]*W[n,k] (+bias)*scale, split-3 bf16.
// A,W given as bf16 hi/lo planes. cp.async double-buffer, ldmatrix frags.
// headmode=1: write planes in head layout. headmode=0: fp32 row-major.
// ---------------------------------------------------------------------------
struct GP {
    const uint32_t *Ah, *Al, *Bh, *Bl;   // planes, rows x 512 words
    const float* bias;
    float* C; uint32_t *Ph, *Pl; float scale;
};
#define GSTAGE_B 40960     // 4 planes x 128 rows x 80B

__global__ __launch_bounds__(256, 2) void gemm_planes(GP a0, GP a1, GP a2, int headmode)
{
    GP g = (blockIdx.z == 0) ? a0 : (blockIdx.z == 1) ? a1 : a2;
    extern __shared__ uint32_t smg[];
    const uint32_t sb = smem_u32(smg);

    const int tid = threadIdx.x;
    const int warp = tid >> 5;
    const int lane = tid & 31;
    const int r4 = lane >> 2, q4 = lane & 3;
    const int m0w = (warp >> 2) * 64;
    const int n0w = (warp & 3) * 32;
    const int mBase = blockIdx.y * 128;
    const int nBase = blockIdx.x * 128;

    const uint32_t* srcA[4] = {
        g.Ah + (size_t)mBase * RWORDS, g.Al + (size_t)mBase * RWORDS,
        g.Bh + (size_t)nBase * RWORDS, g.Bl + (size_t)nBase * RWORDS };

    // frag byte offsets within a stage
    const uint32_t aOffH = (uint32_t)((m0w + (lane & 15)) * 80 + (lane >> 4) * 16);
    const uint32_t aOffL = aOffH + 10240u;
    const int bsel = lane >> 3;
    const uint32_t bOff = (uint32_t)((bsel < 2 ? 20480 : 30720) +
                                     (n0w + (lane & 7)) * 80 + (bsel & 1) * 16);

    float acc[4][4][4];
#pragma unroll
    for (int mf = 0; mf < 4; mf++)
#pragma unroll
        for (int nf = 0; nf < 4; nf++)
#pragma unroll
            for (int c = 0; c < 4; c++) acc[mf][nf][c] = 0.f;

    auto issue = [&](int stage, int ch) {
#pragma unroll
        for (int it = 0; it < 8; it++) {
            int gi = tid + it * 256;
            int pl = gi >> 9, gg = gi & 511;
            int row = gg >> 2, seg = gg & 3;
            const uint32_t* src = srcA[pl] + (size_t)row * RWORDS + ch * 16 + seg * 4;
            uint32_t dst = sb + stage * GSTAGE_B + pl * 10240 + row * 80 + seg * 16;
            cp16(dst, src);
        }
        cp_commit();
    };

    issue(0, 0);
    issue(1, 1);

    for (int ch = 0; ch < 32; ch++) {
        if (ch < 31) cp_wait<1>(); else cp_wait<0>();
        __syncthreads();
        const uint32_t sBase = sb + (ch & 1) * GSTAGE_B;

#pragma unroll
        for (int ks = 0; ks < 2; ks++) {
            const uint32_t ko = ks * 32;
            uint32_t bh[4][2], bl[4][2];
#pragma unroll
            for (int nf = 0; nf < 4; nf++)
                ldsm_x4(bh[nf][0], bh[nf][1], bl[nf][0], bl[nf][1],
                        sBase + bOff + nf * 640 + ko);
#pragma unroll
            for (int mf = 0; mf < 4; mf++) {
                uint32_t ah[4], al[4];
                ldsm_x4(ah[0], ah[1], ah[2], ah[3], sBase + aOffH + mf * 1280 + ko);
                ldsm_x4(al[0], al[1], al[2], al[3], sBase + aOffL + mf * 1280 + ko);
#pragma unroll
                for (int nf = 0; nf < 4; nf++) {
                    MMA16816(acc[mf][nf], ah, bh[nf]);
                    MMA16816(acc[mf][nf], ah, bl[nf]);
                    MMA16816(acc[mf][nf], al, bh[nf]);
                }
            }
        }
        __syncthreads();
        if (ch + 2 < 32) issue(ch & 1, ch + 2);
    }

    // Epilogue
#pragma unroll
    for (int nf = 0; nf < 4; nf++) {
        const int n = nBase + n0w + nf * 8 + q4 * 2;
        const float b0 = __ldg(g.bias + n);
        const float b1 = __ldg(g.bias + n + 1);
#pragma unroll
        for (int mf = 0; mf < 4; mf++) {
#pragma unroll
            for (int half = 0; half < 2; half++) {
                const int m = mBase + m0w + mf * 16 + r4 + half * 8;
                float v0 = (acc[mf][nf][half * 2] + b0) * g.scale;
                float v1 = (acc[mf][nf][half * 2 + 1] + b1) * g.scale;
                if (headmode) {
                    uint32_t hi, lo;
                    cvt_pair(v0, v1, hi, lo);
                    int b = m >> 11, s = m & (NS - 1);
                    int hh = n >> 6, e = n & 63;
                    size_t wo = (((size_t)((b * NH + hh) * NS + s)) * HDIM + e) >> 1;
                    g.Ph[wo] = hi;
                    g.Pl[wo] = lo;
                } else {
                    *(float2*)(g.C + (size_t)m * ND + n) = make_float2(v0, v1);
                }
            }
        }
    }
}

// ---------------------------------------------------------------------------
// Tensor-core flash attention, split-3 QK^T and PV, cp.async K/V ring.
// BQ=128 (8 warps x 16 rows), BKV=64, hd=64. exp2-domain softmax.
// stage layout (bytes): Kh[0] Kl[9216] Vh[18432] Vl[27648]; 2 stages; mask after.
// ---------------------------------------------------------------------------
#define KSTR 36                // u32 words per row (144B)
#define ASTAGE_B 36864         // 4 planes x 64 rows x 144B

__global__ __launch_bounds__(256, 1) void attn_mma(const uint32_t* __restrict__ qh,
                                                   const uint32_t* __restrict__ ql,
                                                   const uint32_t* __restrict__ kh,
                                                   const uint32_t* __restrict__ kl,
                                                   const uint32_t* __restrict__ vh,
                                                   const uint32_t* __restrict__ vl,
                                                   const int* __restrict__ mask,
                                                   uint32_t* __restrict__ ch_out,
                                                   uint32_t* __restrict__ cl_out)
{
    extern __shared__ uint32_t dynsm[];
    const uint32_t sb = smem_u32(dynsm);
    int* sMk = (int*)(dynsm + 2 * (ASTAGE_B / 4));
    uint32_t* sQh = dynsm;                 // phase 1 only
    uint32_t* sQl = dynsm + 128 * KSTR;

    const int tid = threadIdx.x;
    const int warp = tid >> 5;
    const int lane = tid & 31;
    const int r4 = lane >> 2, q4 = lane & 3;
    const int qt = blockIdx.x;     // 0..15
    const int bh = blockIdx.y;     // 0..31
    const int b = bh >> 4, h = bh & 15;
    const size_t headW = (size_t)bh * NS * (HDIM / 2);

    // ---- Phase 1: stage Q planes, load persistent A-frags ----
    {
        const uint32_t* pQh = qh + headW + (size_t)qt * 128 * 32;
        const uint32_t* pQl = ql + headW + (size_t)qt * 128 * 32;
#pragma unroll
        for (int it = 0; it < 8; it++) {
            int gi = tid + it * 256;
            int pl = gi >> 10, gg = gi & 1023;
            int row = gg >> 3, w4 = (gg & 7) * 4;
            uint4 v = *(const uint4*)((pl ? pQl : pQh) + row * 32 + w4);
            *(uint4*)((pl ? sQl : sQh) + row * KSTR + w4) = v;
        }
    }
    __syncthreads();
    uint32_t Qh[4][4], Ql[4][4];
#pragma unroll
    for (int kf = 0; kf < 4; kf++) {
        int off = (16 * warp + r4) * KSTR + 8 * kf + q4;
        Qh[kf][0] = sQh[off];              Qh[kf][1] = sQh[off + 8 * KSTR];
        Qh[kf][2] = sQh[off + 4];          Qh[kf][3] = sQh[off + 8 * KSTR + 4];
        Ql[kf][0] = sQl[off];              Ql[kf][1] = sQl[off + 8 * KSTR];
        Ql[kf][2] = sQl[off + 4];          Ql[kf][3] = sQl[off + 8 * KSTR + 4];
    }
    __syncthreads();   // stage area reusable

    const uint32_t* srcP[4] = {kh + headW, kl + headW, vh + headW, vl + headW};
    auto issue = [&](int stage, int kt) {
#pragma unroll
        for (int it = 0; it < 8; it++) {
            int gi = tid + it * 256;
            int pl = gi >> 9, gg = gi & 511;
            int row = gg >> 3, seg = gg & 7;
            const uint32_t* src = srcP[pl] + (size_t)kt * 2048 + row * 32 + seg * 4;
            uint32_t dst = sb + stage * ASTAGE_B + pl * 9216 + row * 144 + seg * 16;
            cp16(dst, src);
        }
        cp_commit();
    };

    // frag offsets within a stage
    const int ksel = lane >> 3;
    const uint32_t kOff = (uint32_t)((ksel < 2 ? 0 : 9216) +
                                     (lane & 7) * 144 + (ksel & 1) * 16);
    const uint32_t vOff = (uint32_t)((lane < 16 ? 18432 : 27648) + (lane & 15) * 144);

    float O[8][4];
    float mI0 = -INFINITY, mI1 = -INFINITY, lI0 = 0.f, lI1 = 0.f;
#pragma unroll
    for (int nf = 0; nf < 8; nf++)
#pragma unroll
        for (int c = 0; c < 4; c++) O[nf][c] = 0.f;

    const int* mrow = mask + (size_t)b * NS;
    int mkld = (tid < 64) ? mrow[tid] : 0;

    issue(0, 0);
    issue(1, 1);

    for (int kt = 0; kt < 32; kt++) {
        if (tid < 64) sMk[tid] = mkld;
        if (kt < 31) cp_wait<1>(); else cp_wait<0>();
        __syncthreads();
        const uint32_t sStage = sb + (kt & 1) * ASTAGE_B;

        // ---- S = Q K^T (split-3) ----
        float S[8][4];
#pragma unroll
        for (int nf = 0; nf < 8; nf++)
#pragma unroll
            for (int c = 0; c < 4; c++) S[nf][c] = 0.f;
#pragma unroll
        for (int kf = 0; kf < 4; kf++) {
#pragma unroll
            for (int nf = 0; nf < 8; nf++) {
                uint32_t kh2[2], kl2[2];
                ldsm_x4(kh2[0], kh2[1], kl2[0], kl2[1],
                        sStage + kOff + (uint32_t)(nf * 1152 + kf * 32));
                MMA16816(S[nf], Qh[kf], kh2);
                MMA16816(S[nf], Qh[kf], kl2);
                MMA16816(S[nf], Ql[kf], kh2);
            }
        }

        // ---- mask + online softmax (exp2 domain) ----
        float mt0 = -INFINITY, mt1 = -INFINITY;
#pragma unroll
        for (int nf = 0; nf < 8; nf++) {
            int c0 = 8 * nf + 2 * q4;
            if (sMk[c0])     { S[nf][0] = -9e9f; S[nf][2] = -9e9f; }
            if (sMk[c0 + 1]) { S[nf][1] = -9e9f; S[nf][3] = -9e9f; }
            mt0 = fmaxf(mt0, fmaxf(S[nf][0], S[nf][1]));
            mt1 = fmaxf(mt1, fmaxf(S[nf][2], S[nf][3]));
        }
        mt0 = fmaxf(mt0, __shfl_xor_sync(0xffffffffu, mt0, 1));
        mt0 = fmaxf(mt0, __shfl_xor_sync(0xffffffffu, mt0, 2));
        mt1 = fmaxf(mt1, __shfl_xor_sync(0xffffffffu, mt1, 1));
        mt1 = fmaxf(mt1, __shfl_xor_sync(0xffffffffu, mt1, 2));

        float mN0 = fmaxf(mI0, mt0), mN1 = fmaxf(mI1, mt1);
        float f0 = ex2f(mI0 - mN0), f1 = ex2f(mI1 - mN1);
        float rs0 = 0.f, rs1 = 0.f;
#pragma unroll
        for (int nf = 0; nf < 8; nf++) {
            S[nf][0] = ex2f(S[nf][0] - mN0);
            S[nf][1] = ex2f(S[nf][1] - mN0);
            S[nf][2] = ex2f(S[nf][2] - mN1);
            S[nf][3] = ex2f(S[nf][3] - mN1);
            rs0 += S[nf][0] + S[nf][1];
            rs1 += S[nf][2] + S[nf][3];
        }
        rs0 += __shfl_xor_sync(0xffffffffu, rs0, 1);
        rs0 += __shfl_xor_sync(0xffffffffu, rs0, 2);
        rs1 += __shfl_xor_sync(0xffffffffu, rs1, 1);
        rs1 += __shfl_xor_sync(0xffffffffu, rs1, 2);
        lI0 = lI0 * f0 + rs0;
        lI1 = lI1 * f1 + rs1;
        mI0 = mN0; mI1 = mN1;
#pragma unroll
        for (int nf = 0; nf < 8; nf++) {
            O[nf][0] *= f0; O[nf][1] *= f0;
            O[nf][2] *= f1; O[nf][3] *= f1;
        }

        // ---- O += P V (split-3; per-kf P conversion, Vhi/Vlo via one x4) ----
#pragma unroll
        for (int kf = 0; kf < 4; kf++) {
            uint32_t ph[4], pl2[4];
            cvt_pair(S[2*kf][0],     S[2*kf][1],     ph[0], pl2[0]);
            cvt_pair(S[2*kf][2],     S[2*kf][3],     ph[1], pl2[1]);
            cvt_pair(S[2*kf + 1][0], S[2*kf + 1][1], ph[2], pl2[2]);
            cvt_pair(S[2*kf + 1][2], S[2*kf + 1][3], ph[3], pl2[3]);
            uint32_t abase = sStage + vOff + (uint32_t)(kf * 2304);
#pragma unroll
            for (int nf = 0; nf < 8; nf++) {
                uint32_t vh2[2], vl2[2];
                ldsm_x4_t(vh2[0], vh2[1], vl2[0], vl2[1], abase + nf * 16);
                MMA16816(O[nf], ph, vh2);
                MMA16816(O[nf], ph, vl2);
                MMA16816(O[nf], pl2, vh2);
            }
        }

        __syncthreads();
        if (kt + 2 < 32) issue(kt & 1, kt + 2);
        if (kt + 1 < 32 && tid < 64) mkld = mrow[(kt + 1) * 64 + tid];
    }

    // ---- normalize + write ctx planes [b][s][h*64+e] ----
    const float inv0 = 1.f / lI0;
    const float inv1 = 1.f / lI1;
    const int row0 = qt * 128 + 16 * warp + r4;
#pragma unroll
    for (int nf = 0; nf < 8; nf++) {
        uint32_t hi, lo;
        size_t wo0 = (((size_t)(b * NS + row0)) * ND + h * HDIM + 8 * nf + 2 * q4) >> 1;
        size_t wo1 = (((size_t)(b * NS + row0 + 8)) * ND + h * HDIM + 8 * nf + 2 * q4) >> 1;
        cvt_pair(O[nf][0] * inv0, O[nf][1] * inv0, hi, lo);
        ch_out[wo0] = hi; cl_out[wo0] = lo;
        cvt_pair(O[nf][2] * inv1, O[nf][3] * inv1, hi, lo);
        ch_out[wo1] = hi; cl_out[wo1] = lo;
    }
}

extern "C" void kernel_launch(void* const* d_in, const int* in_sizes, int n_in,
                              void* d_out, int out_size)
{
    const float* q  = (const float*)d_in[0];
    const float* k  = (const float*)d_in[1];
    const float* v  = (const float*)d_in[2];
    const int* mask = (const int*)d_in[3];
    const float* Wq = (const float*)d_in[4];
    const float* bq = (const float*)d_in[5];
    const float* Wk = (const float*)d_in[6];
    const float* bk = (const float*)d_in[7];
    const float* Wv = (const float*)d_in[8];
    const float* bv = (const float*)d_in[9];
    const float* Wo = (const float*)d_in[10];
    const float* bo = (const float*)d_in[11];
    float* out = (float*)d_out;

    uint32_t *inqh, *inql, *inkh, *inkl, *invh, *invl, *wh, *wl;
    uint32_t *qh_d, *ql_d, *kh_d, *kl_d, *vh_d, *vl_d, *ch_d, *cl_d;
    cudaGetSymbolAddress((void**)&inqh, g_inqh); cudaGetSymbolAddress((void**)&inql, g_inql);
    cudaGetSymbolAddress((void**)&inkh, g_inkh); cudaGetSymbolAddress((void**)&inkl, g_inkl);
    cudaGetSymbolAddress((void**)&invh, g_invh); cudaGetSymbolAddress((void**)&invl, g_invl);
    cudaGetSymbolAddress((void**)&wh, g_wh);     cudaGetSymbolAddress((void**)&wl, g_wl);
    cudaGetSymbolAddress((void**)&qh_d, g_qh);   cudaGetSymbolAddress((void**)&ql_d, g_ql);
    cudaGetSymbolAddress((void**)&kh_d, g_kh);   cudaGetSymbolAddress((void**)&kl_d, g_kl);
    cudaGetSymbolAddress((void**)&vh_d, g_vh);   cudaGetSymbolAddress((void**)&vl_d, g_vl);
    cudaGetSymbolAddress((void**)&ch_d, g_ch);   cudaGetSymbolAddress((void**)&cl_d, g_cl);

    const int WSTRIDE = ND * RWORDS;   // words per weight plane

    // 1) convert inputs (3 tensors of B*S*D floats)
    cvt_planes<<<dim3(MROWS * ND / 8 / 256, 1, 3), 256>>>(
        q, inqh, inql, k, inkh, inkl, v, invh, invl, q, inqh, inql);
    // 2) convert weights (4 tensors of D*D floats)
    cvt_planes<<<dim3(ND * ND / 8 / 256, 1, 4), 256>>>(
        Wq, wh, wl, Wk, wh + WSTRIDE, wl + WSTRIDE,
        Wv, wh + 2 * WSTRIDE, wl + 2 * WSTRIDE, Wo, wh + 3 * WSTRIDE, wl + 3 * WSTRIDE);

    const int smem_gemm = 2 * GSTAGE_B;                 // 81920
    cudaFuncSetAttribute(gemm_planes, cudaFuncAttributeMaxDynamicSharedMemorySize, smem_gemm);
    const int smem_attn = 2 * ASTAGE_B + 64 * 4;        // 73984
    cudaFuncSetAttribute(attn_mma, cudaFuncAttributeMaxDynamicSharedMemorySize, smem_attn);

    // 3) QKV projections -> head planes (Q pre-scaled)
    GP aq{inqh, inql, wh, wl, bq, nullptr, qh_d, ql_d, QSCALE};
    GP ak{inkh, inkl, wh + WSTRIDE, wl + WSTRIDE, bk, nullptr, kh_d, kl_d, 1.f};
    GP av{invh, invl, wh + 2 * WSTRIDE, wl + 2 * WSTRIDE, bv, nullptr, vh_d, vl_d, 1.f};
    gemm_planes<<<dim3(ND / 128, MROWS / 128, 3), 256, smem_gemm>>>(aq, ak, av, 1);

    // 4) attention -> ctx planes
    attn_mma<<<dim3(NS / 128, NB * NH), 256, smem_attn>>>(qh_d, ql_d, kh_d, kl_d,
                                                          vh_d, vl_d, mask, ch_d, cl_d);

    // 5) output projection (fp32 out)
    GP ao{ch_d, cl_d, wh + 3 * WSTRIDE, wl + 3 * WSTRIDE, bo, out, nullptr, nullptr, 1.f};
    gemm_planes<<<dim3(ND / 128, MROWS / 128, 1), 256, smem_gemm>>>(ao, ao, ao, 0);
}

// round 9
// speedup vs baseline: 1.1015x; 1.1015x over previous
#include <cuda_runtime.h>
#include <cuda_bf16.h>
#include <math.h>
#include <stdint.h>

#define NB 2
#define NS 2048
#define ND 1024
#define NH 16
#define HDIM 64
#define MROWS (NB*NS)
#define RWORDS (ND/2)          // 512 u32 words per 1024-elem bf16 row

// ---- static scratch (no allocations allowed) ----
__device__ uint32_t g_inqh[MROWS*RWORDS], g_inql[MROWS*RWORDS];
__device__ uint32_t g_inkh[MROWS*RWORDS], g_inkl[MROWS*RWORDS];
__device__ uint32_t g_invh[MROWS*RWORDS], g_invl[MROWS*RWORDS];
__device__ uint32_t g_wh[4*ND*RWORDS], g_wl[4*ND*RWORDS];
__device__ uint32_t g_qh[NB*NH*NS*HDIM/2], g_ql[NB*NH*NS*HDIM/2];
__device__ uint32_t g_kh[NB*NH*NS*HDIM/2], g_kl[NB*NH*NS*HDIM/2];
__device__ uint32_t g_vh[NB*NH*NS*HDIM/2], g_vl[NB*NH*NS*HDIM/2];
__device__ uint32_t g_ch[MROWS*RWORDS], g_cl[MROWS*RWORDS];

#define QSCALE 0.18033688011f      // 0.125 * log2(e)

#define MMA16816(c, a, b) \
  asm volatile("mma.sync.aligned.m16n8k16.row.col.f32.bf16.bf16.f32 " \
    "{%0,%1,%2,%3}, {%4,%5,%6,%7}, {%8,%9}, {%0,%1,%2,%3};" \
    : "+f"((c)[0]), "+f"((c)[1]), "+f"((c)[2]), "+f"((c)[3]) \
    : "r"((a)[0]), "r"((a)[1]), "r"((a)[2]), "r"((a)[3]), \
      "r"((b)[0]), "r"((b)[1]))

__device__ __forceinline__ void cvt_pair(float x, float y, uint32_t& hi, uint32_t& lo) {
    __nv_bfloat162 h = __floats2bfloat162_rn(x, y);
    float hx = __bfloat162float(__low2bfloat16(h));
    float hy = __bfloat162float(__high2bfloat16(h));
    __nv_bfloat162 l = __floats2bfloat162_rn(x - hx, y - hy);
    hi = *reinterpret_cast<uint32_t*>(&h);
    lo = *reinterpret_cast<uint32_t*>(&l);
}
__device__ __forceinline__ float ex2f(float x) {
    float y; asm("ex2.approx.ftz.f32 %0, %1;" : "=f"(y) : "f"(x)); return y;
}
__device__ __forceinline__ uint32_t smem_u32(const void* p) {
    uint32_t a;
    asm("{ .reg .u64 t; cvta.to.shared.u64 t, %1; cvt.u32.u64 %0, t; }" : "=r"(a) : "l"(p));
    return a;
}
__device__ __forceinline__ void ldsm_x4(uint32_t& r0, uint32_t& r1, uint32_t& r2, uint32_t& r3,
                                        uint32_t a) {
    asm volatile("ldmatrix.sync.aligned.m8n8.x4.shared.b16 {%0,%1,%2,%3}, [%4];"
                 : "=r"(r0), "=r"(r1), "=r"(r2), "=r"(r3) : "r"(a));
}
__device__ __forceinline__ void ldsm_x4_t(uint32_t& r0, uint32_t& r1, uint32_t& r2, uint32_t& r3,
                                          uint32_t a) {
    asm volatile("ldmatrix.sync.aligned.m8n8.x4.trans.shared.b16 {%0,%1,%2,%3}, [%4];"
                 : "=r"(r0), "=r"(r1), "=r"(r2), "=r"(r3) : "r"(a));
}
__device__ __forceinline__ void cp16(uint32_t dst, const void* src) {
    asm volatile("cp.async.cg.shared.global [%0], [%1], 16;" :: "r"(dst), "l"(src) : "memory");
}
__device__ __forceinline__ void cp_commit() {
    asm volatile("cp.async.commit_group;" ::: "memory");
}
template<int N> __device__ __forceinline__ void cp_wait() {
    asm volatile("cp.async.wait_group %0;" :: "n"(N) : "memory");
}

// ---------------------------------------------------------------------------
// fp32 -> bf16 hi/lo plane converter
// ---------------------------------------------------------------------------
__global__ __launch_bounds__(256) void cvt_planes(
    const float* s0, uint32_t* h0, uint32_t* l0,
    const float* s1, uint32_t* h1, uint32_t* l1,
    const float* s2, uint32_t* h2, uint32_t* l2,
    const float* s3, uint32_t* h3, uint32_t* l3)
{
    const float* s; uint32_t *ph, *pl;
    switch (blockIdx.z) {
        case 0: s = s0; ph = h0; pl = l0; break;
        case 1: s = s1; ph = h1; pl = l1; break;
        case 2: s = s2; ph = h2; pl = l2; break;
        default: s = s3; ph = h3; pl = l3; break;
    }
    int i = blockIdx.x * 256 + threadIdx.x;
    float4 a = ((const float4*)s)[2 * i];
    float4 b = ((const float4*)s)[2 * i + 1];
    uint32_t h[4], l[4];
    cvt_pair(a.x, a.y, h[0], l[0]);
    cvt_pair(a.z, a.w, h[1], l[1]);
    cvt_pair(b.x, b.y, h[2], l[2]);
    cvt_pair(b.z, b.w, h[3], l[3]);
    ((uint4*)ph)[i] = make_uint4(h[0], h[1], h[2], h[3]);
    ((uint4*)pl)[i] = make_uint4(l[0], l[1], l[2], l[3]);
}

// ---------------------------------------------------------------------------
// Plane GEMM (unchanged from R8: cp.async 2-stage, 2 CTAs/SM)
// ---------------------------------------------------------------------------
struct GP {
    const uint32_t *Ah, *Al, *Bh, *Bl;
    const float* bias;
    float* C; uint32_t *Ph, *Pl; float scale;
};
#define GSTAGE_B 40960

__global__ __launch_bounds__(256, 2) void gemm_planes(GP a0, GP a1, GP a2, int headmode)
{
    GP g = (blockIdx.z == 0) ? a0 : (blockIdx.z == 1) ? a1 : a2;
    extern __shared__ uint32_t smg[];
    const uint32_t sb = smem_u32(smg);

    const int tid = threadIdx.x;
    const int warp = tid >> 5;
    const int lane = tid & 31;
    const int r4 = lane >> 2, q4 = lane & 3;
    const int m0w = (warp >> 2) * 64;
    const int n0w = (warp & 3) * 32;
    const int mBase = blockIdx.y * 128;
    const int nBase = blockIdx.x * 128;

    const uint32_t* srcA[4] = {
        g.Ah + (size_t)mBase * RWORDS, g.Al + (size_t)mBase * RWORDS,
        g.Bh + (size_t)nBase * RWORDS, g.Bl + (size_t)nBase * RWORDS };

    const uint32_t aOffH = (uint32_t)((m0w + (lane & 15)) * 80 + (lane >> 4) * 16);
    const uint32_t aOffL = aOffH + 10240u;
    const int bsel = lane >> 3;
    const uint32_t bOff = (uint32_t)((bsel < 2 ? 20480 : 30720) +
                                     (n0w + (lane & 7)) * 80 + (bsel & 1) * 16);

    float acc[4][4][4];
#pragma unroll
    for (int mf = 0; mf < 4; mf++)
#pragma unroll
        for (int nf = 0; nf < 4; nf++)
#pragma unroll
            for (int c = 0; c < 4; c++) acc[mf][nf][c] = 0.f;

    auto issue = [&](int stage, int ch) {
#pragma unroll
        for (int it = 0; it < 8; it++) {
            int gi = tid + it * 256;
            int pl = gi >> 9, gg = gi & 511;
            int row = gg >> 2, seg = gg & 3;
            const uint32_t* src = srcA[pl] + (size_t)row * RWORDS + ch * 16 + seg * 4;
            uint32_t dst = sb + stage * GSTAGE_B + pl * 10240 + row * 80 + seg * 16;
            cp16(dst, src);
        }
        cp_commit();
    };

    issue(0, 0);
    issue(1, 1);

    for (int ch = 0; ch < 32; ch++) {
        if (ch < 31) cp_wait<1>(); else cp_wait<0>();
        __syncthreads();
        const uint32_t sBase = sb + (ch & 1) * GSTAGE_B;

#pragma unroll
        for (int ks = 0; ks < 2; ks++) {
            const uint32_t ko = ks * 32;
            uint32_t bh[4][2], bl[4][2];
#pragma unroll
            for (int nf = 0; nf < 4; nf++)
                ldsm_x4(bh[nf][0], bh[nf][1], bl[nf][0], bl[nf][1],
                        sBase + bOff + nf * 640 + ko);
#pragma unroll
            for (int mf = 0; mf < 4; mf++) {
                uint32_t ah[4], al[4];
                ldsm_x4(ah[0], ah[1], ah[2], ah[3], sBase + aOffH + mf * 1280 + ko);
                ldsm_x4(al[0], al[1], al[2], al[3], sBase + aOffL + mf * 1280 + ko);
#pragma unroll
                for (int nf = 0; nf < 4; nf++) {
                    MMA16816(acc[mf][nf], ah, bh[nf]);
                    MMA16816(acc[mf][nf], ah, bl[nf]);
                    MMA16816(acc[mf][nf], al, bh[nf]);
                }
            }
        }
        __syncthreads();
        if (ch + 2 < 32) issue(ch & 1, ch + 2);
    }

#pragma unroll
    for (int nf = 0; nf < 4; nf++) {
        const int n = nBase + n0w + nf * 8 + q4 * 2;
        const float b0 = __ldg(g.bias + n);
        const float b1 = __ldg(g.bias + n + 1);
#pragma unroll
        for (int mf = 0; mf < 4; mf++) {
#pragma unroll
            for (int half = 0; half < 2; half++) {
                const int m = mBase + m0w + mf * 16 + r4 + half * 8;
                float v0 = (acc[mf][nf][half * 2] + b0) * g.scale;
                float v1 = (acc[mf][nf][half * 2 + 1] + b1) * g.scale;
                if (headmode) {
                    uint32_t hi, lo;
                    cvt_pair(v0, v1, hi, lo);
                    int b = m >> 11, s = m & (NS - 1);
                    int hh = n >> 6, e = n & 63;
                    size_t wo = (((size_t)((b * NH + hh) * NS + s)) * HDIM + e) >> 1;
                    g.Ph[wo] = hi;
                    g.Pl[wo] = lo;
                } else {
                    *(float2*)(g.C + (size_t)m * ND + n) = make_float2(v0, v1);
                }
            }
        }
    }
}

// ---------------------------------------------------------------------------
// Tensor-core flash attention: BQ=64, 128 threads (4 warps x 16 rows),
// 2 CTAs/SM for cross-CTA softmax/MMA overlap. Split-3 QK^T and PV.
// stage layout (bytes): Kh[0] Kl[9216] Vh[18432] Vl[27648]; 2 stages; mask after.
// ---------------------------------------------------------------------------
#define KSTR 36                // u32 words per row (144B)
#define ASTAGE_B 36864         // 4 planes x 64 rows x 144B

__global__ __launch_bounds__(128, 2) void attn_mma(const uint32_t* __restrict__ qh,
                                                   const uint32_t* __restrict__ ql,
                                                   const uint32_t* __restrict__ kh,
                                                   const uint32_t* __restrict__ kl,
                                                   const uint32_t* __restrict__ vh,
                                                   const uint32_t* __restrict__ vl,
                                                   const int* __restrict__ mask,
                                                   uint32_t* __restrict__ ch_out,
                                                   uint32_t* __restrict__ cl_out)
{
    extern __shared__ uint32_t dynsm[];
    const uint32_t sb = smem_u32(dynsm);
    int* sMk = (int*)(dynsm + 2 * (ASTAGE_B / 4));
    uint32_t* sQh = dynsm;                 // phase 1 only (64*36 words each)
    uint32_t* sQl = dynsm + 64 * KSTR;

    const int tid = threadIdx.x;
    const int warp = tid >> 5;
    const int lane = tid & 31;
    const int r4 = lane >> 2, q4 = lane & 3;
    const int qt = blockIdx.x;     // 0..31 (64-row q tiles)
    const int bh = blockIdx.y;     // 0..31
    const int b = bh >> 4, h = bh & 15;
    const size_t headW = (size_t)bh * NS * (HDIM / 2);

    // ---- Phase 1: stage Q planes (64 rows), load persistent A-frags ----
    {
        const uint32_t* pQh = qh + headW + (size_t)qt * 64 * 32;
        const uint32_t* pQl = ql + headW + (size_t)qt * 64 * 32;
#pragma unroll
        for (int it = 0; it < 8; it++) {
            int gi = tid + it * 128;       // 0..1023
            int pl = gi >> 9, gg = gi & 511;
            int row = gg >> 3, w4 = (gg & 7) * 4;
            uint4 v = *(const uint4*)((pl ? pQl : pQh) + row * 32 + w4);
            *(uint4*)((pl ? sQl : sQh) + row * KSTR + w4) = v;
        }
    }
    __syncthreads();
    uint32_t Qh[4][4], Ql[4][4];
#pragma unroll
    for (int kf = 0; kf < 4; kf++) {
        int off = (16 * warp + r4) * KSTR + 8 * kf + q4;
        Qh[kf][0] = sQh[off];              Qh[kf][1] = sQh[off + 8 * KSTR];
        Qh[kf][2] = sQh[off + 4];          Qh[kf][3] = sQh[off + 8 * KSTR + 4];
        Ql[kf][0] = sQl[off];              Ql[kf][1] = sQl[off + 8 * KSTR];
        Ql[kf][2] = sQl[off + 4];          Ql[kf][3] = sQl[off + 8 * KSTR + 4];
    }
    __syncthreads();   // stage area reusable

    const uint32_t* srcP[4] = {kh + headW, kl + headW, vh + headW, vl + headW};
    auto issue = [&](int stage, int kt) {
#pragma unroll
        for (int it = 0; it < 16; it++) {
            int gi = tid + it * 128;       // 0..2047
            int pl = gi >> 9, gg = gi & 511;
            int row = gg >> 3, seg = gg & 7;
            const uint32_t* src = srcP[pl] + (size_t)kt * 2048 + row * 32 + seg * 4;
            uint32_t dst = sb + stage * ASTAGE_B + pl * 9216 + row * 144 + seg * 16;
            cp16(dst, src);
        }
        cp_commit();
    };

    const int ksel = lane >> 3;
    const uint32_t kOff = (uint32_t)((ksel < 2 ? 0 : 9216) +
                                     (lane & 7) * 144 + (ksel & 1) * 16);
    const uint32_t vOff = (uint32_t)((lane < 16 ? 18432 : 27648) + (lane & 15) * 144);

    float O[8][4];
    float mI0 = -INFINITY, mI1 = -INFINITY, lI0 = 0.f, lI1 = 0.f;
#pragma unroll
    for (int nf = 0; nf < 8; nf++)
#pragma unroll
        for (int c = 0; c < 4; c++) O[nf][c] = 0.f;

    const int* mrow = mask + (size_t)b * NS;
    int mkld = (tid < 64) ? mrow[tid] : 0;

    issue(0, 0);
    issue(1, 1);

    for (int kt = 0; kt < 32; kt++) {
        if (tid < 64) sMk[tid] = mkld;        // safe: prev iter ended with sync
        if (kt < 31) cp_wait<1>(); else cp_wait<0>();
        __syncthreads();
        const uint32_t sStage = sb + (kt & 1) * ASTAGE_B;

        // ---- S = Q K^T (split-3) ----
        float S[8][4];
#pragma unroll
        for (int nf = 0; nf < 8; nf++)
#pragma unroll
            for (int c = 0; c < 4; c++) S[nf][c] = 0.f;
#pragma unroll
        for (int kf = 0; kf < 4; kf++) {
#pragma unroll
            for (int nf = 0; nf < 8; nf++) {
                uint32_t kh2[2], kl2[2];
                ldsm_x4(kh2[0], kh2[1], kl2[0], kl2[1],
                        sStage + kOff + (uint32_t)(nf * 1152 + kf * 32));
                MMA16816(S[nf], Qh[kf], kh2);
                MMA16816(S[nf], Qh[kf], kl2);
                MMA16816(S[nf], Ql[kf], kh2);
            }
        }

        // ---- mask + online softmax (exp2 domain) ----
        float mt0 = -INFINITY, mt1 = -INFINITY;
#pragma unroll
        for (int nf = 0; nf < 8; nf++) {
            int c0 = 8 * nf + 2 * q4;
            if (sMk[c0])     { S[nf][0] = -9e9f; S[nf][2] = -9e9f; }
            if (sMk[c0 + 1]) { S[nf][1] = -9e9f; S[nf][3] = -9e9f; }
            mt0 = fmaxf(mt0, fmaxf(S[nf][0], S[nf][1]));
            mt1 = fmaxf(mt1, fmaxf(S[nf][2], S[nf][3]));
        }
        mt0 = fmaxf(mt0, __shfl_xor_sync(0xffffffffu, mt0, 1));
        mt0 = fmaxf(mt0, __shfl_xor_sync(0xffffffffu, mt0, 2));
        mt1 = fmaxf(mt1, __shfl_xor_sync(0xffffffffu, mt1, 1));
        mt1 = fmaxf(mt1, __shfl_xor_sync(0xffffffffu, mt1, 2));

        float mN0 = fmaxf(mI0, mt0), mN1 = fmaxf(mI1, mt1);
        float f0 = ex2f(mI0 - mN0), f1 = ex2f(mI1 - mN1);
        float rs0 = 0.f, rs1 = 0.f;
#pragma unroll
        for (int nf = 0; nf < 8; nf++) {
            S[nf][0] = ex2f(S[nf][0] - mN0);
            S[nf][1] = ex2f(S[nf][1] - mN0);
            S[nf][2] = ex2f(S[nf][2] - mN1);
            S[nf][3] = ex2f(S[nf][3] - mN1);
            rs0 += S[nf][0] + S[nf][1];
            rs1 += S[nf][2] + S[nf][3];
        }
        rs0 += __shfl_xor_sync(0xffffffffu, rs0, 1);
        rs0 += __shfl_xor_sync(0xffffffffu, rs0, 2);
        rs1 += __shfl_xor_sync(0xffffffffu, rs1, 1);
        rs1 += __shfl_xor_sync(0xffffffffu, rs1, 2);
        lI0 = lI0 * f0 + rs0;
        lI1 = lI1 * f1 + rs1;
        mI0 = mN0; mI1 = mN1;
#pragma unroll
        for (int nf = 0; nf < 8; nf++) {
            O[nf][0] *= f0; O[nf][1] *= f0;
            O[nf][2] *= f1; O[nf][3] *= f1;
        }

        // ---- repack P into split hi/lo A-frags (upfront, for ILP) ----
        uint32_t Ph[4][4], Pl[4][4];
#pragma unroll
        for (int kf = 0; kf < 4; kf++) {
            cvt_pair(S[2*kf][0],     S[2*kf][1],     Ph[kf][0], Pl[kf][0]);
            cvt_pair(S[2*kf][2],     S[2*kf][3],     Ph[kf][1], Pl[kf][1]);
            cvt_pair(S[2*kf + 1][0], S[2*kf + 1][1], Ph[kf][2], Pl[kf][2]);
            cvt_pair(S[2*kf + 1][2], S[2*kf + 1][3], Ph[kf][3], Pl[kf][3]);
        }

        // ---- O += P V (split-3; Vhi/Vlo via one ldmatrix.x4.trans) ----
#pragma unroll
        for (int kf = 0; kf < 4; kf++) {
            uint32_t abase = sStage + vOff + (uint32_t)(kf * 2304);
#pragma unroll
            for (int nf = 0; nf < 8; nf++) {
                uint32_t vh2[2], vl2[2];
                ldsm_x4_t(vh2[0], vh2[1], vl2[0], vl2[1], abase + nf * 16);
                MMA16816(O[nf], Ph[kf], vh2);
                MMA16816(O[nf], Ph[kf], vl2);
                MMA16816(O[nf], Pl[kf], vh2);
            }
        }

        __syncthreads();
        if (kt + 2 < 32) issue(kt & 1, kt + 2);
        if (kt + 1 < 32 && tid < 64) mkld = mrow[(kt + 1) * 64 + tid];
    }

    // ---- normalize + write ctx planes [b][s][h*64+e] ----
    const float inv0 = 1.f / lI0;
    const float inv1 = 1.f / lI1;
    const int row0 = qt * 64 + 16 * warp + r4;
#pragma unroll
    for (int nf = 0; nf < 8; nf++) {
        uint32_t hi, lo;
        size_t wo0 = (((size_t)(b * NS + row0)) * ND + h * HDIM + 8 * nf + 2 * q4) >> 1;
        size_t wo1 = (((size_t)(b * NS + row0 + 8)) * ND + h * HDIM + 8 * nf + 2 * q4) >> 1;
        cvt_pair(O[nf][0] * inv0, O[nf][1] * inv0, hi, lo);
        ch_out[wo0] = hi; cl_out[wo0] = lo;
        cvt_pair(O[nf][2] * inv1, O[nf][3] * inv1, hi, lo);
        ch_out[wo1] = hi; cl_out[wo1] = lo;
    }
}

extern "C" void kernel_launch(void* const* d_in, const int* in_sizes, int n_in,
                              void* d_out, int out_size)
{
    const float* q  = (const float*)d_in[0];
    const float* k  = (const float*)d_in[1];
    const float* v  = (const float*)d_in[2];
    const int* mask = (const int*)d_in[3];
    const float* Wq = (const float*)d_in[4];
    const float* bq = (const float*)d_in[5];
    const float* Wk = (const float*)d_in[6];
    const float* bk = (const float*)d_in[7];
    const float* Wv = (const float*)d_in[8];
    const float* bv = (const float*)d_in[9];
    const float* Wo = (const float*)d_in[10];
    const float* bo = (const float*)d_in[11];
    float* out = (float*)d_out;

    uint32_t *inqh, *inql, *inkh, *inkl, *invh, *invl, *wh, *wl;
    uint32_t *qh_d, *ql_d, *kh_d, *kl_d, *vh_d, *vl_d, *ch_d, *cl_d;
    cudaGetSymbolAddress((void**)&inqh, g_inqh); cudaGetSymbolAddress((void**)&inql, g_inql);
    cudaGetSymbolAddress((void**)&inkh, g_inkh); cudaGetSymbolAddress((void**)&inkl, g_inkl);
    cudaGetSymbolAddress((void**)&invh, g_invh); cudaGetSymbolAddress((void**)&invl, g_invl);
    cudaGetSymbolAddress((void**)&wh, g_wh);     cudaGetSymbolAddress((void**)&wl, g_wl);
    cudaGetSymbolAddress((void**)&qh_d, g_qh);   cudaGetSymbolAddress((void**)&ql_d, g_ql);
    cudaGetSymbolAddress((void**)&kh_d, g_kh);   cudaGetSymbolAddress((void**)&kl_d, g_kl);
    cudaGetSymbolAddress((void**)&vh_d, g_vh);   cudaGetSymbolAddress((void**)&vl_d, g_vl);
    cudaGetSymbolAddress((void**)&ch_d, g_ch);   cudaGetSymbolAddress((void**)&cl_d, g_cl);

    const int WSTRIDE = ND * RWORDS;

    cvt_planes<<<dim3(MROWS * ND / 8 / 256, 1, 3), 256>>>(
        q, inqh, inql, k, inkh, inkl, v, invh, invl, q, inqh, inql);
    cvt_planes<<<dim3(ND * ND / 8 / 256, 1, 4), 256>>>(
        Wq, wh, wl, Wk, wh + WSTRIDE, wl + WSTRIDE,
        Wv, wh + 2 * WSTRIDE, wl + 2 * WSTRIDE, Wo, wh + 3 * WSTRIDE, wl + 3 * WSTRIDE);

    const int smem_gemm = 2 * GSTAGE_B;                 // 81920
    cudaFuncSetAttribute(gemm_planes, cudaFuncAttributeMaxDynamicSharedMemorySize, smem_gemm);
    const int smem_attn = 2 * ASTAGE_B + 64 * 4;        // 73984
    cudaFuncSetAttribute(attn_mma, cudaFuncAttributeMaxDynamicSharedMemorySize, smem_attn);

    GP aq{inqh, inql, wh, wl, bq, nullptr, qh_d, ql_d, QSCALE};
    GP ak{inkh, inkl, wh + WSTRIDE, wl + WSTRIDE, bk, nullptr, kh_d, kl_d, 1.f};
    GP av{invh, invl, wh + 2 * WSTRIDE, wl + 2 * WSTRIDE, bv, nullptr, vh_d, vl_d, 1.f};
    gemm_planes<<<dim3(ND / 128, MROWS / 128, 3), 256, smem_gemm>>>(aq, ak, av, 1);

    attn_mma<<<dim3(NS / 64, NB * NH), 128, smem_attn>>>(qh_d, ql_d, kh_d, kl_d,
                                                         vh_d, vl_d, mask, ch_d, cl_d);

    GP ao{ch_d, cl_d, wh + 3 * WSTRIDE, wl + 3 * WSTRIDE, bo, out, nullptr, nullptr, 1.f};
    gemm_planes<<<dim3(ND / 128, MROWS / 128, 1), 256, smem_gemm>>>(ao, ao, ao, 0);
}